// round 14
// baseline (speedup 1.0000x reference)
#include <cuda_runtime.h>
#include <cuda_bf16.h>
#include <cstdint>

#define NN   100000
#define EE   1000000
#define DIN  64
#define DH   128
#define DOUT 64
#define NB_SCAN 391                     // ceil(NN/256)
#define NT1 ((NN + 31) / 32)            // 32-node tiles
#define NTH ((NN + 63) / 64)            // 64-node tiles

typedef unsigned long long ull;

// ----- device scratch (no allocation allowed) -----
__device__ int    g_is64;
__device__ int    g_cnti[NN];
__device__ int    g_bsum[NB_SCAN];
__device__ int    g_off[NN + 1];
__device__ int    g_cur[NN];
__device__ float  g_inv[NN];
__device__ int    g_src[EE];
__device__ int    g_dst[EE];
__device__ int    g_esrc[EE];                      // src sorted by dst bucket
__device__ float4 g_mean1[(size_t)NN * (DIN / 4)]; // mean1; reused as mean2 later
__device__ float4 g_xr[(size_t)NN * (DH / 4)];     // x @ W1r + b1
__device__ float4 g_h4[(size_t)NN * (DH / 4)];
__device__ float4 g_y[(size_t)NN * (DOUT / 4)];

// ---- packed f32x2 helpers (Blackwell FFMA2 — ptxas never emits from C++) ----
__device__ __forceinline__ ull pk2(float a, float b) {
    ull r; asm("mov.b64 %0, {%1, %2};" : "=l"(r) : "f"(a), "f"(b)); return r;
}
__device__ __forceinline__ void upk2(float& a, float& b, ull v) {
    asm("mov.b64 {%0, %1}, %2;" : "=f"(a), "=f"(b) : "l"(v));
}
__device__ __forceinline__ void fma2(ull& d, ull a, ull b) {
    asm("fma.rn.f32x2 %0, %1, %2, %0;" : "+l"(d) : "l"(a), "l"(b));
}

// ------------------- detect edge_index storage width + zero degree histogram
__global__ void detect_zero_kernel(const int* __restrict__ ei) {
    int i = blockIdx.x * blockDim.x + threadIdx.x;
    if (i < NN) g_cnti[i] = 0;
    if (blockIdx.x == 0) {
        __shared__ int any_nonzero;
        if (threadIdx.x == 0) any_nonzero = 0;
        __syncthreads();
        int w = 1 + 2 * threadIdx.x;            // odd words 1..2047
        if (w < 2048 && ei[w] != 0) atomicExch(&any_nonzero, 1);
        __syncthreads();
        if (threadIdx.x == 0) g_is64 = any_nonzero ? 0 : 1;
    }
}

// --------------------------------- convert indices to int32 + degree histogram
__global__ void convert_kernel(const int* __restrict__ ei) {
    int e = blockIdx.x * blockDim.x + threadIdx.x;
    if (e >= EE) return;
    int is64 = g_is64;
    int s = is64 ? ei[2 * e] : ei[e];
    int d = is64 ? ei[2 * (EE + e)] : ei[EE + e];
    s = min(max(s, 0), NN - 1);
    d = min(max(d, 0), NN - 1);
    g_src[e] = s;
    g_dst[e] = d;
    atomicAdd(&g_cnti[d], 1);
}

// ------------------------------------------------------- 2-phase scan
__global__ void scan1_kernel() {
    __shared__ int s[256];
    int i = blockIdx.x * 256 + threadIdx.x;
    s[threadIdx.x] = (i < NN) ? g_cnti[i] : 0;
    __syncthreads();
    for (int d = 128; d > 0; d >>= 1) {
        if (threadIdx.x < d) s[threadIdx.x] += s[threadIdx.x + d];
        __syncthreads();
    }
    if (threadIdx.x == 0) g_bsum[blockIdx.x] = s[0];
}

__global__ void scan3_kernel() {
    __shared__ int s[256];
    __shared__ int sboff[256];
    int t = threadIdx.x;
    int part = 0;
    for (int k = t; k < blockIdx.x; k += 256) part += g_bsum[k];
    sboff[t] = part;
    __syncthreads();
    for (int d = 128; d > 0; d >>= 1) {
        if (t < d) sboff[t] += sboff[t + d];
        __syncthreads();
    }
    int block_off = sboff[0];

    int i = blockIdx.x * 256 + t;
    int c = (i < NN) ? g_cnti[i] : 0;
    s[t] = c;
    __syncthreads();
    for (int d = 1; d < 256; d <<= 1) {
        int v = (t >= d) ? s[t - d] : 0;
        __syncthreads();
        s[t] += v;
        __syncthreads();
    }
    if (i < NN) {
        int off = block_off + s[t] - c;
        g_off[i] = off;
        g_cur[i] = off;
        g_inv[i] = 1.0f / fmaxf((float)c, 1.0f);
    }
    if (i == 0) g_off[NN] = EE;
}

// -------------------------------------------------- bucket-place src by dst
__global__ void place_kernel() {
    int e = blockIdx.x * blockDim.x + threadIdx.x;
    if (e >= EE) return;
    int pos = atomicAdd(&g_cur[g_dst[e]], 1);
    g_esrc[pos] = g_src[e];
}

// ----------------------------------- gather-aggregate: mean1 = mean x[nbrs]
__global__ void __launch_bounds__(256)
agg1_kernel(const float* __restrict__ x) {
    int gwarp = (blockIdx.x * 256 + threadIdx.x) >> 5;
    int lane = threadIdx.x & 31;
    int nw = (gridDim.x * 256) >> 5;
    int chunk = lane & 15, par = lane >> 4;
    const float4* x4 = (const float4*)x;
    for (int node = gwarp; node < NN; node += nw) {
        int s = g_off[node], e = g_off[node + 1];
        float4 acc = make_float4(0.f, 0.f, 0.f, 0.f);
        for (int i = s + par; i < e; i += 2) {
            int src = g_esrc[i];
            float4 v = x4[(size_t)src * 16 + chunk];
            acc.x += v.x; acc.y += v.y; acc.z += v.z; acc.w += v.w;
        }
        acc.x += __shfl_down_sync(0xffffffffu, acc.x, 16);
        acc.y += __shfl_down_sync(0xffffffffu, acc.y, 16);
        acc.z += __shfl_down_sync(0xffffffffu, acc.z, 16);
        acc.w += __shfl_down_sync(0xffffffffu, acc.w, 16);
        if (par == 0) {
            float inv = g_inv[node];
            g_mean1[(size_t)node * 16 + chunk] =
                make_float4(acc.x * inv, acc.y * inv, acc.z * inv, acc.w * inv);
        }
    }
}

// --------------- gather-aggregate 2: mean2 = mean y[nbrs]  (into g_mean1)
__global__ void __launch_bounds__(256)
agg2m_kernel() {
    int gwarp = (blockIdx.x * 256 + threadIdx.x) >> 5;
    int lane = threadIdx.x & 31;
    int nw = (gridDim.x * 256) >> 5;
    int chunk = lane & 15, par = lane >> 4;
    for (int node = gwarp; node < NN; node += nw) {
        int s = g_off[node], e = g_off[node + 1];
        float4 acc = make_float4(0.f, 0.f, 0.f, 0.f);
        for (int i = s + par; i < e; i += 2) {
            int src = g_esrc[i];
            float4 v = g_y[(size_t)src * 16 + chunk];
            acc.x += v.x; acc.y += v.y; acc.z += v.z; acc.w += v.w;
        }
        acc.x += __shfl_down_sync(0xffffffffu, acc.x, 16);
        acc.y += __shfl_down_sync(0xffffffffu, acc.y, 16);
        acc.z += __shfl_down_sync(0xffffffffu, acc.z, 16);
        acc.w += __shfl_down_sync(0xffffffffu, acc.w, 16);
        if (par == 0) {
            float inv = g_inv[node];
            g_mean1[(size_t)node * 16 + chunk] =
                make_float4(acc.x * inv, acc.y * inv, acc.z * inv, acc.w * inv);
        }
    }
}

// ------------------------------- final: out += mean2 + b2
__global__ void final_kernel(const float* __restrict__ b2,
                             float* __restrict__ out) {
    int i = blockIdx.x * blockDim.x + threadIdx.x;   // float4 index
    if (i >= NN * 16) return;
    int c = i & 15;
    float4* out4 = (float4*)out;
    float4 o = out4[i];
    float4 m = g_mean1[i];
    float4 b = *(const float4*)&b2[c * 4];
    out4[i] = make_float4(o.x + m.x + b.x, o.y + m.y + b.y,
                          o.z + m.z + b.z, o.w + m.w + b.w);
}

// -------------------- xr = x @ W1r + b1  (side stream, overlapped w/ prologue)
__global__ void __launch_bounds__(256)
xr_kernel(const float* __restrict__ x,
          const float* __restrict__ W1r,
          const float* __restrict__ b1) {
    extern __shared__ float smem[];
    float* sW  = smem;                 // DIN*DH = 32KB
    float* sb  = sW + DIN * DH;        // 128
    float* sx  = sb + DH;              // 32*DIN = 8KB

    int tid = threadIdx.x;
    for (int k = tid; k < DIN * DH; k += 256) sW[k] = W1r[k];
    if (tid < DH) sb[tid] = b1[tid];

    float* xr = (float*)g_xr;
    int j0 = (tid & 31) * 4;
    int n0 = (tid >> 5) * 4;

    for (int tile = blockIdx.x; tile < NT1; tile += gridDim.x) {
        int base = tile * 32;
        __syncthreads();
        for (int idx = tid; idx < 32 * DIN; idx += 256) {
            int row = base + (idx >> 6);
            sx[idx] = (row < NN) ? x[(size_t)row * DIN + (idx & 63)] : 0.f;
        }
        __syncthreads();

        ull acc[4][2];
        {
            ull b01 = pk2(sb[j0], sb[j0 + 1]);
            ull b23 = pk2(sb[j0 + 2], sb[j0 + 3]);
            #pragma unroll
            for (int i = 0; i < 4; i++) { acc[i][0] = b01; acc[i][1] = b23; }
        }
        #pragma unroll 8
        for (int k = 0; k < DIN; k++) {
            ulonglong2 w = *(const ulonglong2*)&sW[k * DH + j0];
            #pragma unroll
            for (int i = 0; i < 4; i++) {
                float f = sx[(n0 + i) * DIN + k];
                ull pf = pk2(f, f);
                fma2(acc[i][0], pf, w.x);
                fma2(acc[i][1], pf, w.y);
            }
        }
        #pragma unroll
        for (int i = 0; i < 4; i++) {
            int row = base + n0 + i;
            if (row < NN) {
                float a0, a1, a2, a3;
                upk2(a0, a1, acc[i][0]); upk2(a2, a3, acc[i][1]);
                *(float4*)&xr[(size_t)row * DH + j0] = make_float4(a0, a1, a2, a3);
            }
        }
    }
}

// -------------------- layer1m: h = relu(mean1 @ W1l + xr)
__global__ void __launch_bounds__(256)
layer1m_kernel(const float* __restrict__ W1l) {
    extern __shared__ float smem[];
    float* sW = smem;                  // DIN*DH = 32KB
    float* sm = sW + DIN * DH;         // 32*DIN = 8KB

    int tid = threadIdx.x;
    for (int k = tid; k < DIN * DH; k += 256) sW[k] = W1l[k];

    const float* mean1 = (const float*)g_mean1;
    const float* xr = (const float*)g_xr;
    float* h = (float*)g_h4;
    int j0 = (tid & 31) * 4;
    int n0 = (tid >> 5) * 4;

    for (int tile = blockIdx.x; tile < NT1; tile += gridDim.x) {
        int base = tile * 32;
        __syncthreads();
        for (int idx = tid; idx < 32 * DIN; idx += 256) {
            int row = base + (idx >> 6);
            sm[idx] = (row < NN) ? mean1[(size_t)row * DIN + (idx & 63)] : 0.f;
        }
        __syncthreads();

        ull acc[4][2];
        #pragma unroll
        for (int i = 0; i < 4; i++) {
            int row = base + n0 + i;
            float4 v = (row < NN) ? *(const float4*)&xr[(size_t)row * DH + j0]
                                  : make_float4(0.f, 0.f, 0.f, 0.f);
            acc[i][0] = pk2(v.x, v.y);
            acc[i][1] = pk2(v.z, v.w);
        }
        #pragma unroll 8
        for (int k = 0; k < DIN; k++) {
            ulonglong2 w = *(const ulonglong2*)&sW[k * DH + j0];
            #pragma unroll
            for (int i = 0; i < 4; i++) {
                float f = sm[(n0 + i) * DIN + k];
                ull pf = pk2(f, f);
                fma2(acc[i][0], pf, w.x);
                fma2(acc[i][1], pf, w.y);
            }
        }
        #pragma unroll
        for (int i = 0; i < 4; i++) {
            int row = base + n0 + i;
            if (row < NN) {
                float a0, a1, a2, a3;
                upk2(a0, a1, acc[i][0]); upk2(a2, a3, acc[i][1]);
                *(float4*)&h[(size_t)row * DH + j0] =
                    make_float4(fmaxf(a0, 0.f), fmaxf(a1, 0.f),
                                fmaxf(a2, 0.f), fmaxf(a3, 0.f));
            }
        }
    }
}

// ---------------- ymul: y = h @ W2l  (critical path)
__global__ void __launch_bounds__(256, 2)
ymul_kernel(const float* __restrict__ W2l) {
    extern __shared__ float smem[];
    float* sW = smem;                 // DH*DOUT = 32KB
    float* sh = sW + DH * DOUT;       // 64*DH = 32KB

    int tid = threadIdx.x;
    for (int k = tid; k < DH * DOUT; k += 256) sW[k] = W2l[k];

    const float* h = (const float*)g_h4;
    int j0 = (tid & 15) * 4;
    int n0 = (tid >> 4) * 4;

    for (int tile = blockIdx.x; tile < NTH; tile += gridDim.x) {
        int base = tile * 64;
        __syncthreads();
        for (int idx = tid; idx < 64 * DH; idx += 256) {
            int row = base + (idx >> 7);
            sh[idx] = (row < NN) ? h[(size_t)row * DH + (idx & 127)] : 0.f;
        }
        __syncthreads();

        ull ay[4][2];
        #pragma unroll
        for (int i = 0; i < 4; i++) { ay[i][0] = 0ull; ay[i][1] = 0ull; }

        #pragma unroll 4
        for (int k = 0; k < DH; k++) {
            ulonglong2 w = *(const ulonglong2*)&sW[k * DOUT + j0];
            #pragma unroll
            for (int i = 0; i < 4; i++) {
                float f = sh[(n0 + i) * DH + k];
                ull pf = pk2(f, f);
                fma2(ay[i][0], pf, w.x);
                fma2(ay[i][1], pf, w.y);
            }
        }
        #pragma unroll
        for (int i = 0; i < 4; i++) {
            int row = base + n0 + i;
            if (row < NN) {
                float y0, y1, y2, y3;
                upk2(y0, y1, ay[i][0]); upk2(y2, y3, ay[i][1]);
                g_y[(size_t)row * 16 + (j0 >> 2)] = make_float4(y0, y1, y2, y3);
            }
        }
    }
}

// ---------------- hmulr: out = h @ W2r  (side stream, overlaps agg2m)
__global__ void __launch_bounds__(256, 2)
hmulr_kernel(const float* __restrict__ W2r, float* __restrict__ out) {
    extern __shared__ float smem[];
    float* sW = smem;                 // DH*DOUT = 32KB
    float* sh = sW + DH * DOUT;       // 64*DH = 32KB

    int tid = threadIdx.x;
    for (int k = tid; k < DH * DOUT; k += 256) sW[k] = W2r[k];

    const float* h = (const float*)g_h4;
    int j0 = (tid & 15) * 4;
    int n0 = (tid >> 4) * 4;

    for (int tile = blockIdx.x; tile < NTH; tile += gridDim.x) {
        int base = tile * 64;
        __syncthreads();
        for (int idx = tid; idx < 64 * DH; idx += 256) {
            int row = base + (idx >> 7);
            sh[idx] = (row < NN) ? h[(size_t)row * DH + (idx & 127)] : 0.f;
        }
        __syncthreads();

        ull ao[4][2];
        #pragma unroll
        for (int i = 0; i < 4; i++) { ao[i][0] = 0ull; ao[i][1] = 0ull; }

        #pragma unroll 4
        for (int k = 0; k < DH; k++) {
            ulonglong2 w = *(const ulonglong2*)&sW[k * DOUT + j0];
            #pragma unroll
            for (int i = 0; i < 4; i++) {
                float f = sh[(n0 + i) * DH + k];
                ull pf = pk2(f, f);
                fma2(ao[i][0], pf, w.x);
                fma2(ao[i][1], pf, w.y);
            }
        }
        #pragma unroll
        for (int i = 0; i < 4; i++) {
            int row = base + n0 + i;
            if (row < NN) {
                float o0, o1, o2, o3;
                upk2(o0, o1, ao[i][0]); upk2(o2, o3, ao[i][1]);
                *(float4*)&out[(size_t)row * DOUT + j0] = make_float4(o0, o1, o2, o3);
            }
        }
    }
}

// ---------------------------------------------------------------------------
extern "C" void kernel_launch(void* const* d_in, const int* in_sizes, int n_in,
                              void* d_out, int out_size) {
    const float* x   = (const float*)d_in[0];
    const float* W1l = (const float*)d_in[1];
    const float* W1r = (const float*)d_in[2];
    const float* b1  = (const float*)d_in[3];
    const float* W2l = (const float*)d_in[4];
    const float* W2r = (const float*)d_in[5];
    const float* b2  = (const float*)d_in[6];
    const int*   ei  = (const int*)d_in[7];
    float* out = (float*)d_out;

    static cudaStream_t s2 = nullptr;
    static cudaEvent_t ev_fork = nullptr, ev_xr = nullptr, ev_y = nullptr, ev_r = nullptr;
    if (!s2) {
        cudaStreamCreateWithFlags(&s2, cudaStreamNonBlocking);
        cudaEventCreateWithFlags(&ev_fork, cudaEventDisableTiming);
        cudaEventCreateWithFlags(&ev_xr, cudaEventDisableTiming);
        cudaEventCreateWithFlags(&ev_y, cudaEventDisableTiming);
        cudaEventCreateWithFlags(&ev_r, cudaEventDisableTiming);
    }

    const int XR_SMEM  = (DIN * DH + DH + 32 * DIN) * 4;          // ~40.5 KB
    const int L1M_SMEM = (DIN * DH + 32 * DIN) * 4;               // 40 KB
    const int YM_SMEM  = (DH * DOUT + 64 * DH) * 4;               // 64 KB
    cudaFuncSetAttribute(ymul_kernel,  cudaFuncAttributeMaxDynamicSharedMemorySize, YM_SMEM);
    cudaFuncSetAttribute(hmulr_kernel, cudaFuncAttributeMaxDynamicSharedMemorySize, YM_SMEM);

    // Fork 1: xr = x@W1r + b1 overlaps the graph prologue.
    cudaEventRecord(ev_fork, 0);
    cudaStreamWaitEvent(s2, ev_fork, 0);
    xr_kernel<<<592, 256, XR_SMEM, s2>>>(x, W1r, b1);
    cudaEventRecord(ev_xr, s2);

    detect_zero_kernel<<<(NN + 1023) / 1024, 1024>>>(ei);
    convert_kernel<<<(EE + 255) / 256, 256>>>(ei);
    scan1_kernel<<<NB_SCAN, 256>>>();
    scan3_kernel<<<NB_SCAN, 256>>>();
    place_kernel<<<(EE + 255) / 256, 256>>>();
    agg1_kernel<<<1184, 256>>>(x);

    cudaStreamWaitEvent(0, ev_xr, 0);     // join before layer1m needs xr
    layer1m_kernel<<<592, 256, L1M_SMEM>>>(W1l);
    ymul_kernel<<<296, 256, YM_SMEM>>>(W2l);

    // Fork 2: out = h@W2r overlaps agg2m (memory-bound vs FMA-bound).
    cudaEventRecord(ev_y, 0);
    cudaStreamWaitEvent(s2, ev_y, 0);
    hmulr_kernel<<<296, 256, YM_SMEM, s2>>>(W2r, out);
    cudaEventRecord(ev_r, s2);

    agg2m_kernel<<<1184, 256>>>();

    cudaStreamWaitEvent(0, ev_r, 0);      // join before final combines out
    final_kernel<<<(NN * 16 + 255) / 256, 256>>>(b2, out);
}

// round 15
// speedup vs baseline: 1.2363x; 1.2363x over previous
#include <cuda_runtime.h>
#include <cuda_bf16.h>
#include <cstdint>

#define NN   100000
#define EE   1000000
#define DIN  64
#define DH   128
#define DOUT 64
#define NB_SCAN 391                     // ceil(NN/256)
#define NT1 ((NN + 31) / 32)            // 32-node tiles
#define NTH ((NN + 63) / 64)            // hmul tiles of 64 nodes

typedef unsigned long long ull;

// ----- device scratch (no allocation allowed) -----
__device__ int    g_is64;
__device__ int    g_cnti[NN];
__device__ int    g_bsum[NB_SCAN];
__device__ int    g_off[NN + 1];
__device__ int    g_cur[NN];
__device__ float  g_inv[NN];
__device__ int    g_src[EE];
__device__ int    g_dst[EE];
__device__ int    g_esrc[EE];                      // src sorted by dst bucket
__device__ float4 g_mean1[(size_t)NN * (DIN / 4)];
__device__ float4 g_xr[(size_t)NN * (DH / 4)];     // x @ W1r + b1
__device__ float4 g_h4[(size_t)NN * (DH / 4)];
__device__ float4 g_y[(size_t)NN * (DOUT / 4)];

// ---- packed f32x2 helpers (Blackwell FFMA2 — ptxas never emits from C++) ----
__device__ __forceinline__ ull pk2(float a, float b) {
    ull r; asm("mov.b64 %0, {%1, %2};" : "=l"(r) : "f"(a), "f"(b)); return r;
}
__device__ __forceinline__ void upk2(float& a, float& b, ull v) {
    asm("mov.b64 {%0, %1}, %2;" : "=f"(a), "=f"(b) : "l"(v));
}
__device__ __forceinline__ void fma2(ull& d, ull a, ull b) {
    asm("fma.rn.f32x2 %0, %1, %2, %0;" : "+l"(d) : "l"(a), "l"(b));
}

// ------------------- detect edge_index storage width + zero degree histogram
__global__ void detect_zero_kernel(const int* __restrict__ ei) {
    int i = blockIdx.x * blockDim.x + threadIdx.x;
    if (i < NN) g_cnti[i] = 0;
    if (blockIdx.x == 0) {
        __shared__ int any_nonzero;
        if (threadIdx.x == 0) any_nonzero = 0;
        __syncthreads();
        int w = 1 + 2 * threadIdx.x;            // odd words 1..2047
        if (w < 2048 && ei[w] != 0) atomicExch(&any_nonzero, 1);
        __syncthreads();
        if (threadIdx.x == 0) g_is64 = any_nonzero ? 0 : 1;
    }
}

// --------------------------------- convert indices to int32 + degree histogram
__global__ void convert_kernel(const int* __restrict__ ei) {
    int e = blockIdx.x * blockDim.x + threadIdx.x;
    if (e >= EE) return;
    int s, d;
    if (g_is64) {
        const int2* ei2 = (const int2*)ei;      // coalesced 8B loads (low word)
        s = ei2[e].x;
        d = ei2[EE + e].x;
    } else {
        s = ei[e];
        d = ei[EE + e];
    }
    s = min(max(s, 0), NN - 1);
    d = min(max(d, 0), NN - 1);
    g_src[e] = s;
    g_dst[e] = d;
    atomicAdd(&g_cnti[d], 1);
}

// ------------------------------------------------------- 2-phase scan
__global__ void scan1_kernel() {
    __shared__ int s[256];
    int i = blockIdx.x * 256 + threadIdx.x;
    s[threadIdx.x] = (i < NN) ? g_cnti[i] : 0;
    __syncthreads();
    for (int d = 128; d > 0; d >>= 1) {
        if (threadIdx.x < d) s[threadIdx.x] += s[threadIdx.x + d];
        __syncthreads();
    }
    if (threadIdx.x == 0) g_bsum[blockIdx.x] = s[0];
}

__global__ void scan3_kernel() {
    __shared__ int s[256];
    __shared__ int sboff[256];
    int t = threadIdx.x;
    int part = 0;
    for (int k = t; k < blockIdx.x; k += 256) part += g_bsum[k];
    sboff[t] = part;
    __syncthreads();
    for (int d = 128; d > 0; d >>= 1) {
        if (t < d) sboff[t] += sboff[t + d];
        __syncthreads();
    }
    int block_off = sboff[0];

    int i = blockIdx.x * 256 + t;
    int c = (i < NN) ? g_cnti[i] : 0;
    s[t] = c;
    __syncthreads();
    for (int d = 1; d < 256; d <<= 1) {
        int v = (t >= d) ? s[t - d] : 0;
        __syncthreads();
        s[t] += v;
        __syncthreads();
    }
    if (i < NN) {
        int off = block_off + s[t] - c;
        g_off[i] = off;
        g_cur[i] = off;
        g_inv[i] = 1.0f / fmaxf((float)c, 1.0f);
    }
    if (i == 0) g_off[NN] = EE;
}

// -------------------------------------------------- bucket-place src by dst
__global__ void place_kernel() {
    int e = blockIdx.x * blockDim.x + threadIdx.x;
    if (e >= EE) return;
    int pos = atomicAdd(&g_cur[g_dst[e]], 1);
    g_esrc[pos] = g_src[e];
}

// ----------------------------------- gather-aggregate: mean1 = mean x[nbrs]
__global__ void __launch_bounds__(256)
agg1_kernel(const float* __restrict__ x) {
    int gwarp = (blockIdx.x * 256 + threadIdx.x) >> 5;
    int lane = threadIdx.x & 31;
    int nw = (gridDim.x * 256) >> 5;
    int chunk = lane & 15, par = lane >> 4;
    const float4* x4 = (const float4*)x;
    for (int node = gwarp; node < NN; node += nw) {
        int s = g_off[node], e = g_off[node + 1];
        float4 acc = make_float4(0.f, 0.f, 0.f, 0.f);
        for (int i = s + par; i < e; i += 2) {
            int src = g_esrc[i];
            float4 v = x4[(size_t)src * 16 + chunk];
            acc.x += v.x; acc.y += v.y; acc.z += v.z; acc.w += v.w;
        }
        acc.x += __shfl_down_sync(0xffffffffu, acc.x, 16);
        acc.y += __shfl_down_sync(0xffffffffu, acc.y, 16);
        acc.z += __shfl_down_sync(0xffffffffu, acc.z, 16);
        acc.w += __shfl_down_sync(0xffffffffu, acc.w, 16);
        if (par == 0) {
            float inv = g_inv[node];
            g_mean1[(size_t)node * 16 + chunk] =
                make_float4(acc.x * inv, acc.y * inv, acc.z * inv, acc.w * inv);
        }
    }
}

// --------------- gather-aggregate 2 FUSED: out += mean y[nbrs] + b2
__global__ void __launch_bounds__(256)
agg2_kernel(const float* __restrict__ b2, float* __restrict__ out) {
    int gwarp = (blockIdx.x * 256 + threadIdx.x) >> 5;
    int lane = threadIdx.x & 31;
    int nw = (gridDim.x * 256) >> 5;
    int chunk = lane & 15, par = lane >> 4;
    float4* out4 = (float4*)out;
    for (int node = gwarp; node < NN; node += nw) {
        int s = g_off[node], e = g_off[node + 1];
        float4 acc = make_float4(0.f, 0.f, 0.f, 0.f);
        for (int i = s + par; i < e; i += 2) {
            int src = g_esrc[i];
            float4 v = g_y[(size_t)src * 16 + chunk];
            acc.x += v.x; acc.y += v.y; acc.z += v.z; acc.w += v.w;
        }
        acc.x += __shfl_down_sync(0xffffffffu, acc.x, 16);
        acc.y += __shfl_down_sync(0xffffffffu, acc.y, 16);
        acc.z += __shfl_down_sync(0xffffffffu, acc.z, 16);
        acc.w += __shfl_down_sync(0xffffffffu, acc.w, 16);
        if (par == 0) {
            float inv = g_inv[node];
            size_t oi = (size_t)node * 16 + chunk;
            float4 o = out4[oi];
            float4 b = *(const float4*)&b2[chunk * 4];
            out4[oi] = make_float4(o.x + acc.x * inv + b.x,
                                   o.y + acc.y * inv + b.y,
                                   o.z + acc.z * inv + b.z,
                                   o.w + acc.w * inv + b.w);
        }
    }
}

// -------------------- xr = x @ W1r + b1  (side stream, overlapped w/ prologue)
__global__ void __launch_bounds__(256)
xr_kernel(const float* __restrict__ x,
          const float* __restrict__ W1r,
          const float* __restrict__ b1) {
    extern __shared__ float smem[];
    float* sW  = smem;                 // DIN*DH = 32KB
    float* sb  = sW + DIN * DH;        // 128
    float* sx  = sb + DH;              // 32*DIN = 8KB

    int tid = threadIdx.x;
    for (int k = tid; k < DIN * DH; k += 256) sW[k] = W1r[k];
    if (tid < DH) sb[tid] = b1[tid];

    float* xr = (float*)g_xr;
    int j0 = (tid & 31) * 4;
    int n0 = (tid >> 5) * 4;

    for (int tile = blockIdx.x; tile < NT1; tile += gridDim.x) {
        int base = tile * 32;
        __syncthreads();
        for (int idx = tid; idx < 32 * DIN; idx += 256) {
            int row = base + (idx >> 6);
            sx[idx] = (row < NN) ? x[(size_t)row * DIN + (idx & 63)] : 0.f;
        }
        __syncthreads();

        ull acc[4][2];
        {
            ull b01 = pk2(sb[j0], sb[j0 + 1]);
            ull b23 = pk2(sb[j0 + 2], sb[j0 + 3]);
            #pragma unroll
            for (int i = 0; i < 4; i++) { acc[i][0] = b01; acc[i][1] = b23; }
        }
        #pragma unroll 8
        for (int k = 0; k < DIN; k++) {
            ulonglong2 w = *(const ulonglong2*)&sW[k * DH + j0];
            #pragma unroll
            for (int i = 0; i < 4; i++) {
                float f = sx[(n0 + i) * DIN + k];
                ull pf = pk2(f, f);
                fma2(acc[i][0], pf, w.x);
                fma2(acc[i][1], pf, w.y);
            }
        }
        #pragma unroll
        for (int i = 0; i < 4; i++) {
            int row = base + n0 + i;
            if (row < NN) {
                float a0, a1, a2, a3;
                upk2(a0, a1, acc[i][0]); upk2(a2, a3, acc[i][1]);
                *(float4*)&xr[(size_t)row * DH + j0] = make_float4(a0, a1, a2, a3);
            }
        }
    }
}

// -------------------- layer1m: h = relu(mean1 @ W1l + xr)
__global__ void __launch_bounds__(256)
layer1m_kernel(const float* __restrict__ W1l) {
    extern __shared__ float smem[];
    float* sW = smem;                  // DIN*DH = 32KB
    float* sm = sW + DIN * DH;         // 32*DIN = 8KB

    int tid = threadIdx.x;
    for (int k = tid; k < DIN * DH; k += 256) sW[k] = W1l[k];

    const float* mean1 = (const float*)g_mean1;
    const float* xr = (const float*)g_xr;
    float* h = (float*)g_h4;
    int j0 = (tid & 31) * 4;
    int n0 = (tid >> 5) * 4;

    for (int tile = blockIdx.x; tile < NT1; tile += gridDim.x) {
        int base = tile * 32;
        __syncthreads();
        for (int idx = tid; idx < 32 * DIN; idx += 256) {
            int row = base + (idx >> 6);
            sm[idx] = (row < NN) ? mean1[(size_t)row * DIN + (idx & 63)] : 0.f;
        }
        __syncthreads();

        ull acc[4][2];
        #pragma unroll
        for (int i = 0; i < 4; i++) {
            int row = base + n0 + i;
            float4 v = (row < NN) ? *(const float4*)&xr[(size_t)row * DH + j0]
                                  : make_float4(0.f, 0.f, 0.f, 0.f);
            acc[i][0] = pk2(v.x, v.y);
            acc[i][1] = pk2(v.z, v.w);
        }
        #pragma unroll 8
        for (int k = 0; k < DIN; k++) {
            ulonglong2 w = *(const ulonglong2*)&sW[k * DH + j0];
            #pragma unroll
            for (int i = 0; i < 4; i++) {
                float f = sm[(n0 + i) * DIN + k];
                ull pf = pk2(f, f);
                fma2(acc[i][0], pf, w.x);
                fma2(acc[i][1], pf, w.y);
            }
        }
        #pragma unroll
        for (int i = 0; i < 4; i++) {
            int row = base + n0 + i;
            if (row < NN) {
                float a0, a1, a2, a3;
                upk2(a0, a1, acc[i][0]); upk2(a2, a3, acc[i][1]);
                *(float4*)&h[(size_t)row * DH + j0] =
                    make_float4(fmaxf(a0, 0.f), fmaxf(a1, 0.f),
                                fmaxf(a2, 0.f), fmaxf(a3, 0.f));
            }
        }
    }
}

// ---------------- fused: y = h @ W2l ; out_partial = h @ W2r  (R6 shape)
__global__ void __launch_bounds__(256, 2)
hmul_kernel(const float* __restrict__ W2l,
            const float* __restrict__ W2r,
            float* __restrict__ out) {
    extern __shared__ float smem[];
    float* sWl = smem;                  // DH*DOUT = 32KB
    float* sWr = sWl + DH * DOUT;       // 32KB
    float* sh  = sWr + DH * DOUT;       // 64*DH = 32KB

    int tid = threadIdx.x;
    for (int k = tid; k < DH * DOUT; k += 256) { sWl[k] = W2l[k]; sWr[k] = W2r[k]; }

    const float* h = (const float*)g_h4;
    int j0 = (tid & 15) * 4;
    int n0 = (tid >> 4) * 4;

    for (int tile = blockIdx.x; tile < NTH; tile += gridDim.x) {
        int base = tile * 64;
        __syncthreads();
        for (int idx = tid; idx < 64 * DH; idx += 256) {
            int row = base + (idx >> 7);
            sh[idx] = (row < NN) ? h[(size_t)row * DH + (idx & 127)] : 0.f;
        }
        __syncthreads();

        ull ay[4][2], ao[4][2];
        #pragma unroll
        for (int i = 0; i < 4; i++) {
            ay[i][0] = 0ull; ay[i][1] = 0ull;
            ao[i][0] = 0ull; ao[i][1] = 0ull;
        }

        #pragma unroll 4
        for (int k = 0; k < DH; k++) {
            ulonglong2 wl = *(const ulonglong2*)&sWl[k * DOUT + j0];
            ulonglong2 wr = *(const ulonglong2*)&sWr[k * DOUT + j0];
            #pragma unroll
            for (int i = 0; i < 4; i++) {
                float f = sh[(n0 + i) * DH + k];
                ull pf = pk2(f, f);
                fma2(ay[i][0], pf, wl.x);
                fma2(ay[i][1], pf, wl.y);
                fma2(ao[i][0], pf, wr.x);
                fma2(ao[i][1], pf, wr.y);
            }
        }
        #pragma unroll
        for (int i = 0; i < 4; i++) {
            int row = base + n0 + i;
            if (row < NN) {
                float y0, y1, y2, y3, o0, o1, o2, o3;
                upk2(y0, y1, ay[i][0]); upk2(y2, y3, ay[i][1]);
                upk2(o0, o1, ao[i][0]); upk2(o2, o3, ao[i][1]);
                g_y[(size_t)row * 16 + (j0 >> 2)] = make_float4(y0, y1, y2, y3);
                *(float4*)&out[(size_t)row * DOUT + j0] = make_float4(o0, o1, o2, o3);
            }
        }
    }
}

// ---------------------------------------------------------------------------
extern "C" void kernel_launch(void* const* d_in, const int* in_sizes, int n_in,
                              void* d_out, int out_size) {
    const float* x   = (const float*)d_in[0];
    const float* W1l = (const float*)d_in[1];
    const float* W1r = (const float*)d_in[2];
    const float* b1  = (const float*)d_in[3];
    const float* W2l = (const float*)d_in[4];
    const float* W2r = (const float*)d_in[5];
    const float* b2  = (const float*)d_in[6];
    const int*   ei  = (const int*)d_in[7];
    float* out = (float*)d_out;

    static cudaStream_t s2 = nullptr;
    static cudaEvent_t ev_fork = nullptr, ev_xr = nullptr;
    if (!s2) {
        cudaStreamCreateWithFlags(&s2, cudaStreamNonBlocking);
        cudaEventCreateWithFlags(&ev_fork, cudaEventDisableTiming);
        cudaEventCreateWithFlags(&ev_xr, cudaEventDisableTiming);
    }

    const int XR_SMEM  = (DIN * DH + DH + 32 * DIN) * 4;          // ~40.5 KB
    const int L1M_SMEM = (DIN * DH + 32 * DIN) * 4;               // 40 KB
    const int HM_SMEM  = (2 * DH * DOUT + 64 * DH) * 4;           // 96 KB
    cudaFuncSetAttribute(hmul_kernel, cudaFuncAttributeMaxDynamicSharedMemorySize, HM_SMEM);

    // Fork: xr = x@W1r + b1 runs concurrently with the whole graph prologue.
    cudaEventRecord(ev_fork, 0);
    cudaStreamWaitEvent(s2, ev_fork, 0);
    xr_kernel<<<592, 256, XR_SMEM, s2>>>(x, W1r, b1);
    cudaEventRecord(ev_xr, s2);

    detect_zero_kernel<<<(NN + 1023) / 1024, 1024>>>(ei);
    convert_kernel<<<(EE + 255) / 256, 256>>>(ei);
    scan1_kernel<<<NB_SCAN, 256>>>();
    scan3_kernel<<<NB_SCAN, 256>>>();
    place_kernel<<<(EE + 255) / 256, 256>>>();
    agg1_kernel<<<1184, 256>>>(x);

    cudaStreamWaitEvent(0, ev_xr, 0);     // join before layer1m needs xr
    layer1m_kernel<<<592, 256, L1M_SMEM>>>(W1l);
    hmul_kernel<<<296, 256, HM_SMEM>>>(W2l, W2r, out);
    agg2_kernel<<<1184, 256>>>(b2, out);
}

// round 17
// speedup vs baseline: 1.3560x; 1.0969x over previous
#include <cuda_runtime.h>
#include <cuda_bf16.h>
#include <cstdint>

#define NN   100000
#define EE   1000000
#define DIN  64
#define DH   128
#define DOUT 64
#define NB_SCAN 391                     // ceil(NN/256)
#define NT1 ((NN + 31) / 32)            // 32-node tiles
#define NTM ((NN + 63) / 64)            // mma hmul tiles of 64 nodes

typedef unsigned long long ull;

// ----- device scratch (no allocation allowed) -----
__device__ int    g_is64;
__device__ int    g_cnti[NN];
__device__ int    g_bsum[NB_SCAN];
__device__ int    g_off[NN + 1];
__device__ int    g_cur[NN];
__device__ float  g_inv[NN];
__device__ int    g_src[EE];
__device__ int    g_dst[EE];
__device__ int    g_esrc[EE];                      // src sorted by dst bucket
__device__ float4 g_mean1[(size_t)NN * (DIN / 4)];
__device__ float4 g_xr[(size_t)NN * (DH / 4)];     // x @ W1r + b1
__device__ float4 g_h4[(size_t)NN * (DH / 4)];
__device__ float4 g_y[(size_t)NN * (DOUT / 4)];

// ---- packed f32x2 helpers (Blackwell FFMA2) ----
__device__ __forceinline__ ull pk2(float a, float b) {
    ull r; asm("mov.b64 %0, {%1, %2};" : "=l"(r) : "f"(a), "f"(b)); return r;
}
__device__ __forceinline__ void upk2(float& a, float& b, ull v) {
    asm("mov.b64 {%0, %1}, %2;" : "=f"(a), "=f"(b) : "l"(v));
}
__device__ __forceinline__ void fma2(ull& d, ull a, ull b) {
    asm("fma.rn.f32x2 %0, %1, %2, %0;" : "+l"(d) : "l"(a), "l"(b));
}

// ---- mma.sync m16n8k16 bf16 (baseline PTX — legal on compute_103 family) ----
__device__ __forceinline__ void mma16816(float* d, const uint32_t* a, const uint32_t* b) {
    asm volatile("mma.sync.aligned.m16n8k16.row.col.f32.bf16.bf16.f32 "
        "{%0,%1,%2,%3}, {%4,%5,%6,%7}, {%8,%9}, {%0,%1,%2,%3};"
        : "+f"(d[0]), "+f"(d[1]), "+f"(d[2]), "+f"(d[3])
        : "r"(a[0]), "r"(a[1]), "r"(a[2]), "r"(a[3]), "r"(b[0]), "r"(b[1]));
}
// split float pair -> bf16x2 hi word + bf16x2 lo-residual word
__device__ __forceinline__ void split2(float x0, float x1, uint32_t& hi, uint32_t& lo) {
    asm("cvt.rn.bf16x2.f32 %0, %1, %2;" : "=r"(hi) : "f"(x1), "f"(x0));
    float h0 = __uint_as_float(hi << 16);
    float h1 = __uint_as_float(hi & 0xFFFF0000u);
    asm("cvt.rn.bf16x2.f32 %0, %1, %2;" : "=r"(lo) : "f"(x1 - h1), "f"(x0 - h0));
}

// ------------------- detect edge_index storage width + zero degree histogram
__global__ void detect_zero_kernel(const int* __restrict__ ei) {
    int i = blockIdx.x * blockDim.x + threadIdx.x;
    if (i < NN) g_cnti[i] = 0;
    if (blockIdx.x == 0) {
        __shared__ int any_nonzero;
        if (threadIdx.x == 0) any_nonzero = 0;
        __syncthreads();
        int w = 1 + 2 * threadIdx.x;            // odd words 1..2047
        if (w < 2048 && ei[w] != 0) atomicExch(&any_nonzero, 1);
        __syncthreads();
        if (threadIdx.x == 0) g_is64 = any_nonzero ? 0 : 1;
    }
}

// --------------------------------- convert indices to int32 + degree histogram
__global__ void convert_kernel(const int* __restrict__ ei) {
    int e = blockIdx.x * blockDim.x + threadIdx.x;
    if (e >= EE) return;
    int s, d;
    if (g_is64) {
        const int2* ei2 = (const int2*)ei;
        s = ei2[e].x;
        d = ei2[EE + e].x;
    } else {
        s = ei[e];
        d = ei[EE + e];
    }
    s = min(max(s, 0), NN - 1);
    d = min(max(d, 0), NN - 1);
    g_src[e] = s;
    g_dst[e] = d;
    atomicAdd(&g_cnti[d], 1);
}

// ------------------------------------------------------- 2-phase scan
__global__ void scan1_kernel() {
    __shared__ int s[256];
    int i = blockIdx.x * 256 + threadIdx.x;
    s[threadIdx.x] = (i < NN) ? g_cnti[i] : 0;
    __syncthreads();
    for (int d = 128; d > 0; d >>= 1) {
        if (threadIdx.x < d) s[threadIdx.x] += s[threadIdx.x + d];
        __syncthreads();
    }
    if (threadIdx.x == 0) g_bsum[blockIdx.x] = s[0];
}

__global__ void scan3_kernel() {
    __shared__ int s[256];
    __shared__ int sboff[256];
    int t = threadIdx.x;
    int part = 0;
    for (int k = t; k < blockIdx.x; k += 256) part += g_bsum[k];
    sboff[t] = part;
    __syncthreads();
    for (int d = 128; d > 0; d >>= 1) {
        if (t < d) sboff[t] += sboff[t + d];
        __syncthreads();
    }
    int block_off = sboff[0];

    int i = blockIdx.x * 256 + t;
    int c = (i < NN) ? g_cnti[i] : 0;
    s[t] = c;
    __syncthreads();
    for (int d = 1; d < 256; d <<= 1) {
        int v = (t >= d) ? s[t - d] : 0;
        __syncthreads();
        s[t] += v;
        __syncthreads();
    }
    if (i < NN) {
        int off = block_off + s[t] - c;
        g_off[i] = off;
        g_cur[i] = off;
        g_inv[i] = 1.0f / fmaxf((float)c, 1.0f);
    }
    if (i == 0) g_off[NN] = EE;
}

// -------------------------------------------------- bucket-place src by dst
__global__ void place_kernel() {
    int e = blockIdx.x * blockDim.x + threadIdx.x;
    if (e >= EE) return;
    int pos = atomicAdd(&g_cur[g_dst[e]], 1);
    g_esrc[pos] = g_src[e];
}

// ----------------------------------- gather-aggregate: mean1 = mean x[nbrs]
__global__ void __launch_bounds__(256)
agg1_kernel(const float* __restrict__ x) {
    int gwarp = (blockIdx.x * 256 + threadIdx.x) >> 5;
    int lane = threadIdx.x & 31;
    int nw = (gridDim.x * 256) >> 5;
    int chunk = lane & 15, par = lane >> 4;
    const float4* x4 = (const float4*)x;
    for (int node = gwarp; node < NN; node += nw) {
        int s = g_off[node], e = g_off[node + 1];
        float4 acc = make_float4(0.f, 0.f, 0.f, 0.f);
        for (int i = s + par; i < e; i += 2) {
            int src = g_esrc[i];
            float4 v = x4[(size_t)src * 16 + chunk];
            acc.x += v.x; acc.y += v.y; acc.z += v.z; acc.w += v.w;
        }
        acc.x += __shfl_down_sync(0xffffffffu, acc.x, 16);
        acc.y += __shfl_down_sync(0xffffffffu, acc.y, 16);
        acc.z += __shfl_down_sync(0xffffffffu, acc.z, 16);
        acc.w += __shfl_down_sync(0xffffffffu, acc.w, 16);
        if (par == 0) {
            float inv = g_inv[node];
            g_mean1[(size_t)node * 16 + chunk] =
                make_float4(acc.x * inv, acc.y * inv, acc.z * inv, acc.w * inv);
        }
    }
}

// --------------- gather-aggregate 2 FUSED: out += mean y[nbrs] + b2
__global__ void __launch_bounds__(256)
agg2_kernel(const float* __restrict__ b2, float* __restrict__ out) {
    int gwarp = (blockIdx.x * 256 + threadIdx.x) >> 5;
    int lane = threadIdx.x & 31;
    int nw = (gridDim.x * 256) >> 5;
    int chunk = lane & 15, par = lane >> 4;
    float4* out4 = (float4*)out;
    for (int node = gwarp; node < NN; node += nw) {
        int s = g_off[node], e = g_off[node + 1];
        float4 acc = make_float4(0.f, 0.f, 0.f, 0.f);
        for (int i = s + par; i < e; i += 2) {
            int src = g_esrc[i];
            float4 v = g_y[(size_t)src * 16 + chunk];
            acc.x += v.x; acc.y += v.y; acc.z += v.z; acc.w += v.w;
        }
        acc.x += __shfl_down_sync(0xffffffffu, acc.x, 16);
        acc.y += __shfl_down_sync(0xffffffffu, acc.y, 16);
        acc.z += __shfl_down_sync(0xffffffffu, acc.z, 16);
        acc.w += __shfl_down_sync(0xffffffffu, acc.w, 16);
        if (par == 0) {
            float inv = g_inv[node];
            size_t oi = (size_t)node * 16 + chunk;
            float4 o = out4[oi];
            float4 b = *(const float4*)&b2[chunk * 4];
            out4[oi] = make_float4(o.x + acc.x * inv + b.x,
                                   o.y + acc.y * inv + b.y,
                                   o.z + acc.z * inv + b.z,
                                   o.w + acc.w * inv + b.w);
        }
    }
}

// -------------------- xr = x @ W1r + b1  (side stream, overlapped w/ prologue)
__global__ void __launch_bounds__(256)
xr_kernel(const float* __restrict__ x,
          const float* __restrict__ W1r,
          const float* __restrict__ b1) {
    extern __shared__ float smemf[];
    float* sW  = smemf;                // DIN*DH = 32KB
    float* sb  = sW + DIN * DH;        // 128
    float* sx  = sb + DH;              // 32*DIN = 8KB

    int tid = threadIdx.x;
    for (int k = tid; k < DIN * DH; k += 256) sW[k] = W1r[k];
    if (tid < DH) sb[tid] = b1[tid];

    float* xr = (float*)g_xr;
    int j0 = (tid & 31) * 4;
    int n0 = (tid >> 5) * 4;

    for (int tile = blockIdx.x; tile < NT1; tile += gridDim.x) {
        int base = tile * 32;
        __syncthreads();
        for (int idx = tid; idx < 32 * DIN; idx += 256) {
            int row = base + (idx >> 6);
            sx[idx] = (row < NN) ? x[(size_t)row * DIN + (idx & 63)] : 0.f;
        }
        __syncthreads();

        ull acc[4][2];
        {
            ull b01 = pk2(sb[j0], sb[j0 + 1]);
            ull b23 = pk2(sb[j0 + 2], sb[j0 + 3]);
            #pragma unroll
            for (int i = 0; i < 4; i++) { acc[i][0] = b01; acc[i][1] = b23; }
        }
        #pragma unroll 8
        for (int k = 0; k < DIN; k++) {
            ulonglong2 w = *(const ulonglong2*)&sW[k * DH + j0];
            #pragma unroll
            for (int i = 0; i < 4; i++) {
                float f = sx[(n0 + i) * DIN + k];
                ull pf = pk2(f, f);
                fma2(acc[i][0], pf, w.x);
                fma2(acc[i][1], pf, w.y);
            }
        }
        #pragma unroll
        for (int i = 0; i < 4; i++) {
            int row = base + n0 + i;
            if (row < NN) {
                float a0, a1, a2, a3;
                upk2(a0, a1, acc[i][0]); upk2(a2, a3, acc[i][1]);
                *(float4*)&xr[(size_t)row * DH + j0] = make_float4(a0, a1, a2, a3);
            }
        }
    }
}

// -------------------- layer1m: h = relu(mean1 @ W1l + xr)
__global__ void __launch_bounds__(256)
layer1m_kernel(const float* __restrict__ W1l) {
    extern __shared__ float smemf[];
    float* sW = smemf;                 // DIN*DH = 32KB
    float* sm = sW + DIN * DH;         // 32*DIN = 8KB

    int tid = threadIdx.x;
    for (int k = tid; k < DIN * DH; k += 256) sW[k] = W1l[k];

    const float* mean1 = (const float*)g_mean1;
    const float* xr = (const float*)g_xr;
    float* h = (float*)g_h4;
    int j0 = (tid & 31) * 4;
    int n0 = (tid >> 5) * 4;

    for (int tile = blockIdx.x; tile < NT1; tile += gridDim.x) {
        int base = tile * 32;
        __syncthreads();
        for (int idx = tid; idx < 32 * DIN; idx += 256) {
            int row = base + (idx >> 6);
            sm[idx] = (row < NN) ? mean1[(size_t)row * DIN + (idx & 63)] : 0.f;
        }
        __syncthreads();

        ull acc[4][2];
        #pragma unroll
        for (int i = 0; i < 4; i++) {
            int row = base + n0 + i;
            float4 v = (row < NN) ? *(const float4*)&xr[(size_t)row * DH + j0]
                                  : make_float4(0.f, 0.f, 0.f, 0.f);
            acc[i][0] = pk2(v.x, v.y);
            acc[i][1] = pk2(v.z, v.w);
        }
        #pragma unroll 8
        for (int k = 0; k < DIN; k++) {
            ulonglong2 w = *(const ulonglong2*)&sW[k * DH + j0];
            #pragma unroll
            for (int i = 0; i < 4; i++) {
                float f = sm[(n0 + i) * DIN + k];
                ull pf = pk2(f, f);
                fma2(acc[i][0], pf, w.x);
                fma2(acc[i][1], pf, w.y);
            }
        }
        #pragma unroll
        for (int i = 0; i < 4; i++) {
            int row = base + n0 + i;
            if (row < NN) {
                float a0, a1, a2, a3;
                upk2(a0, a1, acc[i][0]); upk2(a2, a3, acc[i][1]);
                *(float4*)&h[(size_t)row * DH + j0] =
                    make_float4(fmaxf(a0, 0.f), fmaxf(a1, 0.f),
                                fmaxf(a2, 0.f), fmaxf(a3, 0.f));
            }
        }
    }
}

// ---------------- mma.sync hmul: y = h@W2l ; out = h@W2r (bf16 2-split)
// 64-node tile, 128 thr = 4 warps (m16 each).
// smem words (4B): sWh[128n][64kw] swizzled, sWlo same, sHh[64r][64kw], sHl.
// Swizzle: word index w stored at (w ^ (4*(row&7))) — fragment LDS conflict-free.
__global__ void __launch_bounds__(128)
hmul_mma_kernel(const float* __restrict__ W2l,
                const float* __restrict__ W2r,
                float* __restrict__ out) {
    extern __shared__ uint32_t smw[];
    uint32_t* sWh = smw;                 // 128*64 = 32KB
    uint32_t* sWl = sWh + 128 * 64;      // 32KB
    uint32_t* sHh = sWl + 128 * 64;      // 64*64 = 16KB
    uint32_t* sHl = sHh + 64 * 64;       // 16KB

    int tid = threadIdx.x;               // 128
    int wid = tid >> 5, lane = tid & 31;
    int g = lane >> 2, tg = lane & 3;
    int wrow = wid * 16;

    // Stage weights once: n 0..63 = W2l col n; n 64..127 = W2r col n-64.
    for (int idx = tid; idx < 64 * 128; idx += 128) {
        int w = idx >> 7, n = idx & 127;          // consecutive tid -> consecutive n
        const float* W = (n < 64) ? W2l : W2r;
        int nc = n & 63;
        float w0 = W[(2 * w) * DOUT + nc];
        float w1 = W[(2 * w + 1) * DOUT + nc];
        uint32_t hi, lo;
        split2(w0, w1, hi, lo);
        int sw = w ^ (4 * (n & 7));
        sWh[n * 64 + sw] = hi;
        sWl[n * 64 + sw] = lo;
    }

    const float2* h2 = (const float2*)g_h4;
    float2* y2 = (float2*)g_y;
    float2* o2 = (float2*)out;

    for (int tile = blockIdx.x; tile < NTM; tile += gridDim.x) {
        int base = tile * 64;
        __syncthreads();    // previous tile's fragment reads done
        for (int idx = tid; idx < 64 * 64; idx += 128) {
            int r = idx >> 6, w = idx & 63;
            int row = base + r;
            float2 v = (row < NN) ? h2[(size_t)row * 64 + w] : make_float2(0.f, 0.f);
            uint32_t hi, lo;
            split2(v.x, v.y, hi, lo);
            int sw = w ^ (4 * (r & 7));
            sHh[r * 64 + sw] = hi;
            sHl[r * 64 + sw] = lo;
        }
        __syncthreads();

        #pragma unroll
        for (int p = 0; p < 2; p++) {
            float d[8][4];
            #pragma unroll
            for (int nb = 0; nb < 8; nb++)
                #pragma unroll
                for (int c = 0; c < 4; c++) d[nb][c] = 0.f;

            #pragma unroll
            for (int kb = 0; kb < 8; kb++) {
                int kw0 = (kb * 8 + tg) ^ (4 * g);
                int kw1 = (kb * 8 + 4 + tg) ^ (4 * g);
                uint32_t ah[4], al[4];
                ah[0] = sHh[(wrow + g) * 64 + kw0];
                ah[1] = sHh[(wrow + g + 8) * 64 + kw0];
                ah[2] = sHh[(wrow + g) * 64 + kw1];
                ah[3] = sHh[(wrow + g + 8) * 64 + kw1];
                al[0] = sHl[(wrow + g) * 64 + kw0];
                al[1] = sHl[(wrow + g + 8) * 64 + kw0];
                al[2] = sHl[(wrow + g) * 64 + kw1];
                al[3] = sHl[(wrow + g + 8) * 64 + kw1];
                #pragma unroll
                for (int nb = 0; nb < 8; nb++) {
                    int n = p * 64 + nb * 8 + g;
                    uint32_t bh[2], bl[2];
                    bh[0] = sWh[n * 64 + kw0];
                    bh[1] = sWh[n * 64 + kw1];
                    bl[0] = sWl[n * 64 + kw0];
                    bl[1] = sWl[n * 64 + kw1];
                    mma16816(d[nb], ah, bh);
                    mma16816(d[nb], ah, bl);
                    mma16816(d[nb], al, bh);
                }
            }
            int r0 = base + wrow + g, r1 = r0 + 8;
            #pragma unroll
            for (int nb = 0; nb < 8; nb++) {
                int c2 = nb * 4 + tg;     // float2 column index (of 32)
                if (p == 0) {
                    if (r0 < NN) y2[(size_t)r0 * 32 + c2] = make_float2(d[nb][0], d[nb][1]);
                    if (r1 < NN) y2[(size_t)r1 * 32 + c2] = make_float2(d[nb][2], d[nb][3]);
                } else {
                    if (r0 < NN) o2[(size_t)r0 * 32 + c2] = make_float2(d[nb][0], d[nb][1]);
                    if (r1 < NN) o2[(size_t)r1 * 32 + c2] = make_float2(d[nb][2], d[nb][3]);
                }
            }
        }
    }
}

// ---------------------------------------------------------------------------
extern "C" void kernel_launch(void* const* d_in, const int* in_sizes, int n_in,
                              void* d_out, int out_size) {
    const float* x   = (const float*)d_in[0];
    const float* W1l = (const float*)d_in[1];
    const float* W1r = (const float*)d_in[2];
    const float* b1  = (const float*)d_in[3];
    const float* W2l = (const float*)d_in[4];
    const float* W2r = (const float*)d_in[5];
    const float* b2  = (const float*)d_in[6];
    const int*   ei  = (const int*)d_in[7];
    float* out = (float*)d_out;

    static cudaStream_t s2 = nullptr;
    static cudaEvent_t ev_fork = nullptr, ev_xr = nullptr;
    if (!s2) {
        cudaStreamCreateWithFlags(&s2, cudaStreamNonBlocking);
        cudaEventCreateWithFlags(&ev_fork, cudaEventDisableTiming);
        cudaEventCreateWithFlags(&ev_xr, cudaEventDisableTiming);
    }

    const int XR_SMEM  = (DIN * DH + DH + 32 * DIN) * 4;          // ~40.5 KB
    const int L1M_SMEM = (DIN * DH + 32 * DIN) * 4;               // 40 KB
    const int MM_SMEM  = (2 * 128 * 64 + 2 * 64 * 64) * 4;        // 96 KB
    cudaFuncSetAttribute(hmul_mma_kernel, cudaFuncAttributeMaxDynamicSharedMemorySize, MM_SMEM);

    // Fork: xr = x@W1r + b1 runs concurrently with the whole graph prologue.
    cudaEventRecord(ev_fork, 0);
    cudaStreamWaitEvent(s2, ev_fork, 0);
    xr_kernel<<<592, 256, XR_SMEM, s2>>>(x, W1r, b1);
    cudaEventRecord(ev_xr, s2);

    detect_zero_kernel<<<(NN + 1023) / 1024, 1024>>>(ei);
    convert_kernel<<<(EE + 255) / 256, 256>>>(ei);
    scan1_kernel<<<NB_SCAN, 256>>>();
    scan3_kernel<<<NB_SCAN, 256>>>();
    place_kernel<<<(EE + 255) / 256, 256>>>();
    agg1_kernel<<<1184, 256>>>(x);

    cudaStreamWaitEvent(0, ev_xr, 0);     // join before layer1m needs xr
    layer1m_kernel<<<592, 256, L1M_SMEM>>>(W1l);
    hmul_mma_kernel<<<296, 128, MM_SMEM>>>(W2l, W2r, out);
    agg2_kernel<<<1184, 256>>>(b2, out);
}